// round 3
// baseline (speedup 1.0000x reference)
#include <cuda_runtime.h>
#include <cstdint>

#define NUM_HEADS 4
#define OUT_DIM   256
#define B_ROWS    64
#define HID       512
#define Q         256          // NUM_HEADS * B_ROWS
#define TOPK      16
#define BN        64           // keys per score tile
#define BK        32           // k-chunk
#define GRID2     296          // blocks for the score kernel (2 per SM)
#define BSTRIDE   66           // padded B_s row stride (floats)
#define SSTRIDE   65           // padded S_s row stride (floats)

// ---------------- device scratch (no allocations allowed) ----------------
__device__ __align__(16) float q_glob[Q * OUT_DIM];
__device__ float candS[GRID2 * Q * TOPK];
__device__ int   candI[GRID2 * Q * TOPK];

// ---------------- packed f32x2 helpers (Blackwell FFMA2) ------------------
__device__ __forceinline__ unsigned long long ffma2(unsigned long long a,
                                                    unsigned long long b,
                                                    unsigned long long c) {
    unsigned long long d;
    asm("fma.rn.f32x2 %0, %1, %2, %3;" : "=l"(d) : "l"(a), "l"(b), "l"(c));
    return d;
}
__device__ __forceinline__ unsigned long long dup2(float x) {
    unsigned u = __float_as_uint(x);
    unsigned long long d;
    asm("mov.b64 %0, {%1, %2};" : "=l"(d) : "r"(u), "r"(u));
    return d;
}
__device__ __forceinline__ float neg_inf() { return __int_as_float(0xff800000); }

// =====================================================================
// Kernel 1: q = layer_norm(hidden @ Wp + bp), reshaped to [Q, D]
// one block per query row qi = h*64 + b; thread d computes one output dim
// =====================================================================
__global__ void proj_ln_kernel(const float* __restrict__ hidden,
                               const float* __restrict__ Wp,
                               const float* __restrict__ bp) {
    __shared__ float hid[HID];
    __shared__ float red[256];
    int qi = blockIdx.x;
    int h = qi >> 6, b = qi & 63;
    int d = threadIdx.x;

    hid[d]       = hidden[b * HID + d];
    hid[d + 256] = hidden[b * HID + 256 + d];
    __syncthreads();

    int col = h * OUT_DIM + d;            // column in Wp [512, 1024]
    float s = bp[col];
#pragma unroll 8
    for (int k = 0; k < HID; ++k)
        s = fmaf(hid[k], Wp[k * (NUM_HEADS * OUT_DIM) + col], s);

    // mean
    red[d] = s; __syncthreads();
    for (int st = 128; st > 0; st >>= 1) {
        if (d < st) red[d] += red[d + st];
        __syncthreads();
    }
    float mean = red[0] * (1.0f / OUT_DIM);
    __syncthreads();

    // variance (biased, centered)
    float c = s - mean;
    red[d] = c * c; __syncthreads();
    for (int st = 128; st > 0; st >>= 1) {
        if (d < st) red[d] += red[d + st];
        __syncthreads();
    }
    float var = red[0] * (1.0f / OUT_DIM);

    q_glob[qi * OUT_DIM + d] = c * rsqrtf(var + 1e-5f);
}

// =====================================================================
// Kernel 2: scores = q @ mem_feat^T fused with per-query top-16.
// BM=256 (all queries), BN=64 keys per tile, BK=32.
// 256 threads: tq = tid&31 -> 8 query rows (tq*8..), tn = tid>>5 -> 8 keys.
// f32x2-packed accumulators (pairs along n).  One thread = one query for
// the selection phase over the padded score tile in smem.
// =====================================================================
extern __shared__ float smem2[];

__global__ __launch_bounds__(256, 2)
void score_topk_kernel(const float* __restrict__ mem, int nkeys, int ntiles) {
    float* A_s = smem2;                        // [BK][256]
    float* B_s = A_s + BK * 256;               // [BK][BSTRIDE]
    float* S_s = B_s + BK * BSTRIDE;           // [Q][SSTRIDE]

    int tid = threadIdx.x;
    int tq = tid & 31, tn = tid >> 5;

    float topS[TOPK]; int topI[TOPK];
#pragma unroll
    for (int i = 0; i < TOPK; ++i) { topS[i] = neg_inf(); topI[i] = 0x7fffffff; }

    int bn  = tid >> 2;          // B-load: key row within tile (0..63)
    int bkc = (tid & 3) * 8;     // B-load: k sub-chunk (0,8,16,24)

    for (int tile = blockIdx.x; tile < ntiles; tile += GRID2) {
        int nbase = tile * BN;

        unsigned long long acc[8][4];
#pragma unroll
        for (int i = 0; i < 8; ++i)
#pragma unroll
            for (int j = 0; j < 4; ++j) acc[i][j] = 0ull;

#pragma unroll 1
        for (int kt = 0; kt < OUT_DIM / BK; ++kt) {
            int k0 = kt * BK;
            __syncthreads();   // protect smem from previous phase

            // --- load A tile (transpose to [k][q]); thread owns query tid
            {
                const float4* src =
                    reinterpret_cast<const float4*>(q_glob + tid * OUT_DIM + k0);
#pragma unroll
                for (int v = 0; v < 8; ++v) {
                    float4 t4 = src[v];
                    A_s[(v * 4 + 0) * 256 + tid] = t4.x;
                    A_s[(v * 4 + 1) * 256 + tid] = t4.y;
                    A_s[(v * 4 + 2) * 256 + tid] = t4.z;
                    A_s[(v * 4 + 3) * 256 + tid] = t4.w;
                }
            }
            // --- load B tile ([k][n], zero-padded past nkeys)
            {
                int row = nbase + bn;
                float4 t0 = make_float4(0.f, 0.f, 0.f, 0.f), t1 = t0;
                if (row < nkeys) {
                    const float4* src = reinterpret_cast<const float4*>(
                        mem + (size_t)row * OUT_DIM + k0 + bkc);
                    t0 = src[0]; t1 = src[1];
                }
                B_s[(bkc + 0) * BSTRIDE + bn] = t0.x;
                B_s[(bkc + 1) * BSTRIDE + bn] = t0.y;
                B_s[(bkc + 2) * BSTRIDE + bn] = t0.z;
                B_s[(bkc + 3) * BSTRIDE + bn] = t0.w;
                B_s[(bkc + 4) * BSTRIDE + bn] = t1.x;
                B_s[(bkc + 5) * BSTRIDE + bn] = t1.y;
                B_s[(bkc + 6) * BSTRIDE + bn] = t1.z;
                B_s[(bkc + 7) * BSTRIDE + bn] = t1.w;
            }
            __syncthreads();

            // --- compute: 8q x 8n micro-tile, n packed in f32x2 pairs
#pragma unroll 8
            for (int k = 0; k < BK; ++k) {
                const float4 a0 = *reinterpret_cast<const float4*>(A_s + k * 256 + tq * 8);
                const float4 a1 = *reinterpret_cast<const float4*>(A_s + k * 256 + tq * 8 + 4);
                const unsigned long long b0 =
                    *reinterpret_cast<const unsigned long long*>(B_s + k * BSTRIDE + tn * 8);
                const unsigned long long b1 =
                    *reinterpret_cast<const unsigned long long*>(B_s + k * BSTRIDE + tn * 8 + 2);
                const unsigned long long b2 =
                    *reinterpret_cast<const unsigned long long*>(B_s + k * BSTRIDE + tn * 8 + 4);
                const unsigned long long b3 =
                    *reinterpret_cast<const unsigned long long*>(B_s + k * BSTRIDE + tn * 8 + 6);
                unsigned long long ad[8] = {dup2(a0.x), dup2(a0.y), dup2(a0.z), dup2(a0.w),
                                            dup2(a1.x), dup2(a1.y), dup2(a1.z), dup2(a1.w)};
#pragma unroll
                for (int i = 0; i < 8; ++i) {
                    acc[i][0] = ffma2(ad[i], b0, acc[i][0]);
                    acc[i][1] = ffma2(ad[i], b1, acc[i][1]);
                    acc[i][2] = ffma2(ad[i], b2, acc[i][2]);
                    acc[i][3] = ffma2(ad[i], b3, acc[i][3]);
                }
            }
        }

        // --- scatter scores to padded S_s
#pragma unroll
        for (int i = 0; i < 8; ++i) {
            int qrow = tq * 8 + i;
#pragma unroll
            for (int j = 0; j < 4; ++j) {
                unsigned long long v = acc[i][j];
                S_s[qrow * SSTRIDE + tn * 8 + 2 * j]     = __uint_as_float((unsigned)(v & 0xffffffffu));
                S_s[qrow * SSTRIDE + tn * 8 + 2 * j + 1] = __uint_as_float((unsigned)(v >> 32));
            }
        }
        __syncthreads();

        // --- selection: thread tid owns query tid, scans its score row
        {
            int jmax = min(BN, nkeys - nbase);
            const float* srow = S_s + tid * SSTRIDE;
            for (int j = 0; j < jmax; ++j) {
                float s = srow[j];
                int   n = nbase + j;
                if (s > topS[TOPK - 1] ||
                    (s == topS[TOPK - 1] && n < topI[TOPK - 1])) {
                    float cs = s; int ci = n;
#pragma unroll
                    for (int p = 0; p < TOPK; ++p) {
                        bool sw = (cs > topS[p]) || (cs == topS[p] && ci < topI[p]);
                        if (sw) {
                            float ts = topS[p]; int ti = topI[p];
                            topS[p] = cs; topI[p] = ci;
                            cs = ts; ci = ti;
                        }
                    }
                }
            }
        }
    }

    // --- emit per-block sorted candidate lists
    {
        int base = (blockIdx.x * Q + tid) * TOPK;
#pragma unroll
        for (int i = 0; i < TOPK; ++i) { candS[base + i] = topS[i]; candI[base + i] = topI[i]; }
    }
}

// =====================================================================
// Kernel 3: per-query merge of GRID2 sorted candidate lists (32-lane
// pre-merge + threshold-pruned final merge), then write
//   [top_scores | top_idx(as float) | top_feats]  into d_out.
// one block per query, 256 threads (thread = feature dim for the gather)
// =====================================================================
__global__ void merge_gather_kernel(const float* __restrict__ mem,
                                    float* __restrict__ out) {
    __shared__ float ls[32 * TOPK];
    __shared__ int   li[32 * TOPK];
    __shared__ float fs[TOPK];
    __shared__ int   fi[TOPK];

    int q = blockIdx.x, t = threadIdx.x;

    if (t < 32) {
        float bs[TOPK]; int bi[TOPK];
#pragma unroll
        for (int i = 0; i < TOPK; ++i) { bs[i] = neg_inf(); bi[i] = 0x7fffffff; }
        for (int g = t; g < GRID2; g += 32) {
            int base = (g * Q + q) * TOPK;
#pragma unroll 1
            for (int i = 0; i < TOPK; ++i) {
                float s = candS[base + i]; int id = candI[base + i];
                bool qual = (s > bs[TOPK - 1]) ||
                            (s == bs[TOPK - 1] && id < bi[TOPK - 1]);
                if (!qual) break;   // list is sorted: rest cannot qualify
                float cs = s; int ci = id;
#pragma unroll
                for (int p = 0; p < TOPK; ++p) {
                    bool sw = (cs > bs[p]) || (cs == bs[p] && ci < bi[p]);
                    if (sw) { float ts = bs[p]; int ti = bi[p];
                              bs[p] = cs; bi[p] = ci; cs = ts; ci = ti; }
                }
            }
        }
#pragma unroll
        for (int i = 0; i < TOPK; ++i) { ls[t * TOPK + i] = bs[i]; li[t * TOPK + i] = bi[i]; }
    }
    __syncthreads();

    if (t == 0) {
        float bs[TOPK]; int bi[TOPK];
#pragma unroll
        for (int i = 0; i < TOPK; ++i) { bs[i] = neg_inf(); bi[i] = 0x7fffffff; }
        for (int l = 0; l < 32; ++l) {
#pragma unroll 1
            for (int i = 0; i < TOPK; ++i) {
                float s = ls[l * TOPK + i]; int id = li[l * TOPK + i];
                bool qual = (s > bs[TOPK - 1]) ||
                            (s == bs[TOPK - 1] && id < bi[TOPK - 1]);
                if (!qual) break;
                float cs = s; int ci = id;
#pragma unroll
                for (int p = 0; p < TOPK; ++p) {
                    bool sw = (cs > bs[p]) || (cs == bs[p] && ci < bi[p]);
                    if (sw) { float ts = bs[p]; int ti = bi[p];
                              bs[p] = cs; bi[p] = ci; cs = ts; ci = ti; }
                }
            }
        }
#pragma unroll
        for (int i = 0; i < TOPK; ++i) { fs[i] = bs[i]; fi[i] = bi[i]; }
    }
    __syncthreads();

    // outputs: [Q*TOPK scores][Q*TOPK idx][Q*TOPK*D feats]
    if (t < TOPK) {
        out[q * TOPK + t]             = fs[t];
        out[Q * TOPK + q * TOPK + t]  = (float)fi[t];
    }
#pragma unroll 1
    for (int i = 0; i < TOPK; ++i) {
        int row = fi[i];
        out[2 * Q * TOPK + ((size_t)(q * TOPK + i)) * OUT_DIM + t] =
            mem[(size_t)row * OUT_DIM + t];
    }
}

// =====================================================================
extern "C" void kernel_launch(void* const* d_in, const int* in_sizes, int n_in,
                              void* d_out, int out_size) {
    const float* hidden = (const float*)d_in[0];   // [64, 512]
    const float* Wp     = (const float*)d_in[1];   // [512, 1024]
    const float* bp     = (const float*)d_in[2];   // [1024]
    const float* mem    = (const float*)d_in[3];   // [N, 256]
    int nkeys  = in_sizes[3] / OUT_DIM;
    int ntiles = (nkeys + BN - 1) / BN;

    proj_ln_kernel<<<Q, 256>>>(hidden, Wp, bp);

    const int smem_bytes = (BK * 256 + BK * BSTRIDE + Q * SSTRIDE) * (int)sizeof(float);
    cudaFuncSetAttribute(score_topk_kernel,
                         cudaFuncAttributeMaxDynamicSharedMemorySize, smem_bytes);
    score_topk_kernel<<<GRID2, 256, smem_bytes>>>(mem, nkeys, ntiles);

    merge_gather_kernel<<<Q, 256>>>(mem, (float*)d_out);
}

// round 7
// speedup vs baseline: 1.7790x; 1.7790x over previous
#include <cuda_runtime.h>
#include <cuda_bf16.h>
#include <cstdint>

#define NUM_HEADS 4
#define DDIM      256
#define HID       512
#define NQ        256
#define TOPK      16
#define BN        128           // keys per score tile
#define NCL       148           // score-kernel CTAs (= candidate lists/query)
#define CAND      40            // rescore candidate pool per query

// ---- score-kernel dynamic smem layout (bytes) ----
#define A_OFF     0
#define A_BYTES   (256*512)             /* 256 q rows x 256 bf16 (swizzled) = 131072 */
#define B_OFF     A_BYTES
#define B_STAGE   (128*80)              /* 128 keys x 32 bf16, rows padded to 80B */
#define S_OFF     (B_OFF + 2*B_STAGE)   /* 151552 */
#define S_STRIDE  67                    /* floats (odd-ish: conflict-free scan) */
#define SMEM_SC   (S_OFF + 256*S_STRIDE*4)  /* 220160 */

// ---- device scratch (no allocations allowed) ----
__device__ __align__(16) float q_glob[NQ * DDIM];
__device__ float candS[(size_t)NQ * NCL * TOPK];
__device__ int   candI[(size_t)NQ * NCL * TOPK];

__device__ __forceinline__ uint32_t smem_u32(const void* p) {
    uint32_t a;
    asm("{ .reg .u64 t; cvta.to.shared.u64 t, %1; cvt.u32.u64 %0, t; }" : "=r"(a) : "l"(p));
    return a;
}
__device__ __forceinline__ float neg_inf() { return __int_as_float(0xff800000); }

#define LDSM_X4(r0,r1,r2,r3, addr) \
    asm volatile("ldmatrix.sync.aligned.m8n8.x4.shared.b16 {%0,%1,%2,%3}, [%4];" \
        : "=r"(r0), "=r"(r1), "=r"(r2), "=r"(r3) : "r"(addr))
#define MMA_BF16(d, a, b) \
    asm volatile("mma.sync.aligned.m16n8k16.row.col.f32.bf16.bf16.f32 " \
        "{%0,%1,%2,%3}, {%4,%5,%6,%7}, {%8,%9}, {%0,%1,%2,%3};" \
        : "+f"((d)[0]), "+f"((d)[1]), "+f"((d)[2]), "+f"((d)[3]) \
        : "r"((a)[0]), "r"((a)[1]), "r"((a)[2]), "r"((a)[3]), "r"((b)[0]), "r"((b)[1]))

__device__ __forceinline__ uint32_t pack_bf16x2(float lo, float hi) {
    __nv_bfloat162 h = __floats2bfloat162_rn(lo, hi);
    return *reinterpret_cast<uint32_t*>(&h);
}

// =====================================================================
// Kernel 1: q = layer_norm(hidden @ Wp + bp) -> q_glob [256,256]
// 64 blocks: h = bid>>4, bb = bid&15 (4 batch rows each); 256 threads.
// =====================================================================
__global__ void proj_ln_kernel(const float* __restrict__ hidden,
                               const float* __restrict__ Wp,
                               const float* __restrict__ bp) {
    __shared__ float hidT[HID * 4];      // [k][r]
    __shared__ float wr1[8], wr2[8];
    int h = blockIdx.x >> 4, bb = blockIdx.x & 15;
    int t = threadIdx.x, lane = t & 31, wid = t >> 5;

#pragma unroll
    for (int i = 0; i < 8; ++i) {
        int idx = t + i * 256;           // 0..2047
        int k = idx >> 2, r = idx & 3;
        hidT[k * 4 + r] = hidden[(bb * 4 + r) * HID + k];
    }
    __syncthreads();

    int col = h * DDIM + t;
    float a0 = 0.f, a1 = 0.f, a2 = 0.f, a3 = 0.f;
#pragma unroll 4
    for (int k = 0; k < HID; ++k) {
        float4 hv = *reinterpret_cast<const float4*>(&hidT[k * 4]);
        float w = Wp[k * (NUM_HEADS * DDIM) + col];
        a0 = fmaf(hv.x, w, a0); a1 = fmaf(hv.y, w, a1);
        a2 = fmaf(hv.z, w, a2); a3 = fmaf(hv.w, w, a3);
    }
    float bias = bp[col];
    float x[4] = {a0 + bias, a1 + bias, a2 + bias, a3 + bias};

#pragma unroll 1
    for (int r = 0; r < 4; ++r) {
        float v = x[r], v2 = v * v;
#pragma unroll
        for (int o = 16; o; o >>= 1) {
            v  += __shfl_xor_sync(0xffffffffu, v,  o);
            v2 += __shfl_xor_sync(0xffffffffu, v2, o);
        }
        if (lane == 0) { wr1[wid] = v; wr2[wid] = v2; }
        __syncthreads();
        float s1 = 0.f, s2 = 0.f;
#pragma unroll
        for (int w = 0; w < 8; ++w) { s1 += wr1[w]; s2 += wr2[w]; }
        float mean = s1 * (1.0f / DDIM);
        float var  = s2 * (1.0f / DDIM) - mean * mean;
        q_glob[(h * 64 + bb * 4 + r) * DDIM + t] = (x[r] - mean) * rsqrtf(var + 1e-5f);
        __syncthreads();
    }
}

// =====================================================================
// Kernel 2: bf16 mma.sync score GEMM fused with per-query top-16.
// Block tile: 256 queries x 128 keys, K staged 32 at a time (8 stages).
// 8 warps: wm = wid&3 (64 q-rows), wn = wid>>2 (64 key-cols). Warp tile
// 64x64 via m16n8k16, acc fp32. A resident bf16 smem (XOR swizzle);
// B double-buffered LDG(fp32)->cvt->STS(bf16, 80B rows). B fragments via
// NON-transposed ldmatrix (storage is [n][k]). Epilogue: two 64-col
// halves through smem S; thread = query for top-16 insertion.
// =====================================================================
__global__ void __launch_bounds__(256, 1)
score_kernel(const float* __restrict__ mem, int nkeys, int ntiles) {
    extern __shared__ __align__(16) char smem[];
    uint32_t sb = smem_u32(smem);
    int tid = threadIdx.x, lane = tid & 31, wid = tid >> 5;
    int wm = wid & 3, wn = wid >> 2;

    // ---- fill A (bf16, swizzled) from q_glob ----
#pragma unroll 4
    for (int idx = tid; idx < 256 * 128; idx += 256) {
        int m = idx >> 7, kp = idx & 127;
        float2 v = *reinterpret_cast<const float2*>(q_glob + m * DDIM + 2 * kp);
        uint32_t off = (uint32_t)(A_OFF + m * 512 + ((kp * 4) ^ ((m & 7) << 4)));
        *reinterpret_cast<uint32_t*>(smem + off) = pack_bf16x2(v.x, v.y);
    }
    __syncthreads();

    // ---- per-thread invariants ----
    int ldrow = tid >> 1;                 // B-load: key row within tile (0..127)
    int ldk   = (tid & 1) * 16;           // B-load: k sub-chunk (floats)
    uint32_t sts_base = (uint32_t)(B_OFF + ldrow * 80 + (tid & 1) * 32);

    uint32_t a_rowbyte = (uint32_t)(A_OFF + (wm * 64 + (lane & 15)) * 512);
    uint32_t a_swz   = (uint32_t)((lane & 7) << 4);
    uint32_t a_koff2 = (uint32_t)((lane >> 4) * 16);     // bytes
    int sub = lane >> 3;
    uint32_t b_lane = (uint32_t)(((wn * 64 + (sub >> 1) * 8 + (lane & 7)) * 80) +
                                 ((sub & 1) * 8) * 2);

    float topS[TOPK]; int topI[TOPK];
#pragma unroll
    for (int i = 0; i < TOPK; ++i) { topS[i] = neg_inf(); topI[i] = 0x7fffffff; }

    for (int tile = blockIdx.x; tile < ntiles; tile += NCL) {
        int keybase = tile * BN;
        float acc[4][8][4];
#pragma unroll
        for (int mt = 0; mt < 4; ++mt)
#pragma unroll
            for (int nt = 0; nt < 8; ++nt)
#pragma unroll
                for (int e = 0; e < 4; ++e) acc[mt][nt][e] = 0.f;

        // prefetch stage 0
        float4 pf[4];
        {
            int key = keybase + ldrow;
            if (key < nkeys) {
                const float4* src = reinterpret_cast<const float4*>(
                    mem + (size_t)key * DDIM + ldk);
#pragma unroll
                for (int v = 0; v < 4; ++v) pf[v] = src[v];
            } else {
#pragma unroll
                for (int v = 0; v < 4; ++v) pf[v] = make_float4(0.f, 0.f, 0.f, 0.f);
            }
        }

#pragma unroll 1
        for (int s = 0; s < 8; ++s) {
            int buf = s & 1;
            // convert + STS current stage
            {
                uint32_t u[8];
                u[0] = pack_bf16x2(pf[0].x, pf[0].y); u[1] = pack_bf16x2(pf[0].z, pf[0].w);
                u[2] = pack_bf16x2(pf[1].x, pf[1].y); u[3] = pack_bf16x2(pf[1].z, pf[1].w);
                u[4] = pack_bf16x2(pf[2].x, pf[2].y); u[5] = pack_bf16x2(pf[2].z, pf[2].w);
                u[6] = pack_bf16x2(pf[3].x, pf[3].y); u[7] = pack_bf16x2(pf[3].z, pf[3].w);
                uint4* dst = reinterpret_cast<uint4*>(smem + sts_base + buf * B_STAGE);
                dst[0] = make_uint4(u[0], u[1], u[2], u[3]);
                dst[1] = make_uint4(u[4], u[5], u[6], u[7]);
            }
            __syncthreads();
            // prefetch next stage
            if (s < 7) {
                int key = keybase + ldrow;
                if (key < nkeys) {
                    const float4* src = reinterpret_cast<const float4*>(
                        mem + (size_t)key * DDIM + (s + 1) * 32 + ldk);
#pragma unroll
                    for (int v = 0; v < 4; ++v) pf[v] = src[v];
                } else {
#pragma unroll
                    for (int v = 0; v < 4; ++v) pf[v] = make_float4(0.f, 0.f, 0.f, 0.f);
                }
            }
            // mma over this stage (2 x k16)
            uint32_t bbuf = sb + (uint32_t)(B_OFF + buf * B_STAGE);
#pragma unroll
            for (int kk = 0; kk < 2; ++kk) {
                uint32_t kbyte = (uint32_t)((s * 32 + kk * 16) * 2);
                uint32_t a[4][4];
#pragma unroll
                for (int mt = 0; mt < 4; ++mt)
                    LDSM_X4(a[mt][0], a[mt][1], a[mt][2], a[mt][3],
                            sb + a_rowbyte + (uint32_t)(mt * 8192) +
                            ((kbyte + a_koff2) ^ a_swz));
                uint32_t b[8][2];
#pragma unroll
                for (int p = 0; p < 4; ++p)
                    LDSM_X4(b[2*p][0], b[2*p][1], b[2*p+1][0], b[2*p+1][1],
                            bbuf + b_lane + (uint32_t)(p * 1280 + kk * 32));
#pragma unroll
                for (int mt = 0; mt < 4; ++mt)
#pragma unroll
                    for (int nt = 0; nt < 8; ++nt)
                        MMA_BF16(acc[mt][nt], a[mt], b[nt]);
            }
        }

        // ---- epilogue: two 64-col halves ----
        float* S = reinterpret_cast<float*>(smem + S_OFF);
#pragma unroll 1
        for (int half = 0; half < 2; ++half) {
            if (wn == half) {
#pragma unroll
                for (int mt = 0; mt < 4; ++mt) {
                    int row = wm * 64 + mt * 16 + (lane >> 2);
#pragma unroll
                    for (int nt = 0; nt < 8; ++nt) {
                        int col = nt * 8 + (lane & 3) * 2;
                        S[row * S_STRIDE + col]           = acc[mt][nt][0];
                        S[row * S_STRIDE + col + 1]       = acc[mt][nt][1];
                        S[(row + 8) * S_STRIDE + col]     = acc[mt][nt][2];
                        S[(row + 8) * S_STRIDE + col + 1] = acc[mt][nt][3];
                    }
                }
            }
            __syncthreads();
            int kb = keybase + half * 64;
            int jmax = nkeys - kb; if (jmax > 64) jmax = 64;
            const float* srow = S + tid * S_STRIDE;
            for (int j = 0; j < jmax; ++j) {
                float sc = srow[j];
                int key = kb + j;
                if (sc > topS[TOPK - 1] ||
                    (sc == topS[TOPK - 1] && key < topI[TOPK - 1])) {
                    float cs = sc; int ci = key;
#pragma unroll
                    for (int p = 0; p < TOPK; ++p) {
                        bool sw = (cs > topS[p]) || (cs == topS[p] && ci < topI[p]);
                        if (sw) { float ts = topS[p]; int ti = topI[p];
                                  topS[p] = cs; topI[p] = ci; cs = ts; ci = ti; }
                    }
                }
            }
            __syncthreads();
        }
    }

    // ---- emit per-CTA sorted candidate lists (thread = query) ----
    size_t base = ((size_t)tid * NCL + blockIdx.x) * TOPK;
#pragma unroll
    for (int i = 0; i < TOPK; ++i) { candS[base + i] = topS[i]; candI[base + i] = topI[i]; }
}

// =====================================================================
// Kernel 3: merge 148 sorted bf16 candidate lists -> top-40, exact fp32
// rescore, final top-16 + gather. block = query, 128 threads.
// =====================================================================
__global__ void merge_rescore_kernel(const float* __restrict__ mem,
                                     float* __restrict__ out, int nkeys) {
    __shared__ float ls[32 * TOPK];
    __shared__ int   li[32 * TOPK];
    __shared__ float csm[CAND];
    __shared__ int   cim[CAND];
    __shared__ float qrow[DDIM];
    __shared__ float rs[CAND];
    __shared__ float fs[TOPK];
    __shared__ int   fi[TOPK];

    int q = blockIdx.x, t = threadIdx.x;   // 128 threads
    qrow[t]       = q_glob[q * DDIM + t];
    qrow[t + 128] = q_glob[q * DDIM + 128 + t];

    if (t < 32) {
        float bs[TOPK]; int bi[TOPK];
#pragma unroll
        for (int i = 0; i < TOPK; ++i) { bs[i] = neg_inf(); bi[i] = 0x7fffffff; }
        for (int cl = t; cl < NCL; cl += 32) {
            size_t base = ((size_t)q * NCL + cl) * TOPK;
#pragma unroll 1
            for (int i = 0; i < TOPK; ++i) {
                float s = candS[base + i]; int id = candI[base + i];
                if (!(s > bs[TOPK - 1] || (s == bs[TOPK - 1] && id < bi[TOPK - 1]))) break;
                float cs = s; int ci = id;
#pragma unroll
                for (int p = 0; p < TOPK; ++p) {
                    bool sw = (cs > bs[p]) || (cs == bs[p] && ci < bi[p]);
                    if (sw) { float ts = bs[p]; int ti = bi[p];
                              bs[p] = cs; bi[p] = ci; cs = ts; ci = ti; }
                }
            }
        }
#pragma unroll
        for (int i = 0; i < TOPK; ++i) { ls[t * TOPK + i] = bs[i]; li[t * TOPK + i] = bi[i]; }
    }
    __syncthreads();

    if (t == 0) {
        for (int i = 0; i < CAND; ++i) { csm[i] = neg_inf(); cim[i] = 0x7fffffff; }
        for (int l = 0; l < 32; ++l) {
#pragma unroll 1
            for (int i = 0; i < TOPK; ++i) {
                float s = ls[l * TOPK + i]; int id = li[l * TOPK + i];
                if (!(s > csm[CAND - 1] || (s == csm[CAND - 1] && id < cim[CAND - 1]))) break;
                int p = CAND - 1;
                while (p > 0 && (s > csm[p - 1] || (s == csm[p - 1] && id < cim[p - 1]))) {
                    csm[p] = csm[p - 1]; cim[p] = cim[p - 1]; --p;
                }
                csm[p] = s; cim[p] = id;
            }
        }
    }
    __syncthreads();

    // exact fp32 rescore; warp w handles candidates w, w+4, ...
    {
        int w = t >> 5, l = t & 31;
        for (int k = w; k < CAND; k += 4) {
            int id = cim[k];
            float sum = 0.f;
            if (id >= 0 && id < nkeys) {
                const float* row = mem + (size_t)id * DDIM;
#pragma unroll
                for (int d = l; d < DDIM; d += 32) sum = fmaf(qrow[d], row[d], sum);
            }
#pragma unroll
            for (int o = 16; o; o >>= 1) sum += __shfl_xor_sync(0xffffffffu, sum, o);
            if (l == 0) rs[k] = (id >= 0 && id < nkeys) ? sum : neg_inf();
        }
    }
    __syncthreads();

    if (t == 0) {
        float bs[TOPK]; int bi[TOPK];
#pragma unroll
        for (int i = 0; i < TOPK; ++i) { bs[i] = neg_inf(); bi[i] = 0x7fffffff; }
        for (int k = 0; k < CAND; ++k) {
            float s = rs[k]; int id = cim[k];
            if (s > bs[TOPK - 1] || (s == bs[TOPK - 1] && id < bi[TOPK - 1])) {
                float cs = s; int ci = id;
#pragma unroll
                for (int p = 0; p < TOPK; ++p) {
                    bool sw = (cs > bs[p]) || (cs == bs[p] && ci < bi[p]);
                    if (sw) { float ts = bs[p]; int ti = bi[p];
                              bs[p] = cs; bi[p] = ci; cs = ts; ci = ti; }
                }
            }
        }
#pragma unroll
        for (int i = 0; i < TOPK; ++i) { fs[i] = bs[i]; fi[i] = bi[i]; }
    }
    __syncthreads();

    if (t < TOPK) {
        out[q * TOPK + t]             = fs[t];
        out[NQ * TOPK + q * TOPK + t] = (float)fi[t];
    }
#pragma unroll 1
    for (int i = 0; i < TOPK; ++i) {
        int row = fi[i];
        size_t ob = (size_t)2 * NQ * TOPK + ((size_t)(q * TOPK + i)) * DDIM;
        out[ob + t]       = mem[(size_t)row * DDIM + t];
        out[ob + 128 + t] = mem[(size_t)row * DDIM + 128 + t];
    }
}

// =====================================================================
extern "C" void kernel_launch(void* const* d_in, const int* in_sizes, int n_in,
                              void* d_out, int out_size) {
    const float* hidden = (const float*)d_in[0];   // [64, 512]
    const float* Wp     = (const float*)d_in[1];   // [512, 1024]
    const float* bp     = (const float*)d_in[2];   // [1024]
    const float* mem    = (const float*)d_in[3];   // [N, 256]
    int nkeys  = in_sizes[3] / DDIM;
    int ntiles = (nkeys + BN - 1) / BN;

    proj_ln_kernel<<<64, 256>>>(hidden, Wp, bp);

    cudaFuncSetAttribute(score_kernel, cudaFuncAttributeMaxDynamicSharedMemorySize,
                         SMEM_SC);
    score_kernel<<<NCL, 256, SMEM_SC>>>(mem, nkeys, ntiles);

    merge_rescore_kernel<<<NQ, 128>>>(mem, (float*)d_out, nkeys);
}